// round 3
// baseline (speedup 1.0000x reference)
#include <cuda_runtime.h>
#include <cstdint>

#define BB 128
#define SSEQ 16
#define TT 256
#define ZZ 512
#define HC 1024
#define EE 512
#define HD 1024
#define VV 1024

// ---------------- scratch (device globals; zero-init at module load) ----------------
__device__ float g_zero[BB * HD];                       // never written: stays zero
__device__ float g_cin[SSEQ * BB * HC];
__device__ float g_gxc[SSEQ * BB * 4 * HC];
__device__ float g_condh[SSEQ * BB * HC];
__device__ float g_emb[SSEQ * BB * EE];
__device__ float g_gxe[SSEQ * BB * 4 * HD];
__device__ float g_gx[TT * BB * 4 * HD];
__device__ float g_h0[TT * BB * HD];
__device__ float g_h1[TT * BB * HD];
__device__ float g_gates[BB * 4 * HD];
__device__ float g_cbuf[BB * HD];
__device__ float g_bsum[3 * 4 * HD];

// grid-barrier state (monotonic generation; count self-resets)
__device__ volatile unsigned int g_bar_gen;
__device__ unsigned int g_bar_cnt;

// ---------------- packed fp32x2 helpers (SASS FFMA2 path) ----------------
__device__ __forceinline__ unsigned long long ffma2(unsigned long long a,
                                                    unsigned long long b,
                                                    unsigned long long c) {
    unsigned long long d;
    asm("fma.rn.f32x2 %0, %1, %2, %3;" : "=l"(d) : "l"(a), "l"(b), "l"(c));
    return d;
}
__device__ __forceinline__ unsigned long long pk2(float x, float y) {
    unsigned long long r;
    asm("mov.b64 %0, {%1, %2};" : "=l"(r) : "f"(x), "f"(y));
    return r;
}
__device__ __forceinline__ float2 upk2(unsigned long long v) {
    float2 d;
    asm("mov.b64 {%0, %1}, %2;" : "=f"(d.x), "=f"(d.y) : "l"(v));
    return d;
}

// ---------------- generic NT GEMM (big, fully parallel projections) ----------------
// amode: 0 = A row m;  1 = z-gather (m = s*BB+b reads z row b*SSEQ+s);
//        2 = prev-x   (m = t*BB+b reads x row b*TT+t-1, zeros at t==0)
// cinmode: 0 = Cin row m; 1 = Cin row (t>>4)*BB+b
// cmode:   0 = C row m;   1 = C row (b*TT+t)
// act:     0 = none;      1 = tanh
__global__ __launch_bounds__(256)
void gemm_nt(const float* __restrict__ A, const float* __restrict__ W,
             const float* __restrict__ bias, const float* __restrict__ Cin,
             float* __restrict__ C,
             int M, int N, int K, int ldw,
             int amode, int cinmode, int cmode, int act)
{
    __shared__ unsigned long long Ad[16][64];
    __shared__ float Ws[16][64];

    const int tid = threadIdx.x;
    const int m0 = blockIdx.y << 6;
    const int n0 = blockIdx.x << 6;

    const int li = tid >> 2;
    const int lk = (tid & 3) << 2;

    const int m = m0 + li;
    const float* arow;
    if (amode == 0) {
        arow = A + (size_t)m * K;
    } else if (amode == 1) {
        int b = m & (BB - 1), s = m >> 7;
        arow = A + ((size_t)b * SSEQ + s) * K;
    } else {
        int t = m >> 7, b = m & (BB - 1);
        arow = (t == 0) ? g_zero : A + ((size_t)b * TT + (t - 1)) * K;
    }
    arow += lk;
    const float* wrow = W + (size_t)(n0 + li) * ldw + lk;

    const int nkt = K >> 4;
    float4 a_reg = *(const float4*)arow;
    float4 w_reg = *(const float4*)wrow;

    const int ty = tid >> 4;
    const int tx = tid & 15;

    unsigned long long acc[4][2];
#pragma unroll
    for (int r = 0; r < 4; ++r) { acc[r][0] = 0ull; acc[r][1] = 0ull; }

    for (int kt = 0; kt < nkt; ++kt) {
        Ad[lk + 0][li] = pk2(a_reg.x, a_reg.x);
        Ad[lk + 1][li] = pk2(a_reg.y, a_reg.y);
        Ad[lk + 2][li] = pk2(a_reg.z, a_reg.z);
        Ad[lk + 3][li] = pk2(a_reg.w, a_reg.w);
        Ws[lk + 0][li] = w_reg.x;
        Ws[lk + 1][li] = w_reg.y;
        Ws[lk + 2][li] = w_reg.z;
        Ws[lk + 3][li] = w_reg.w;
        __syncthreads();
        if (kt + 1 < nkt) {
            a_reg = *(const float4*)(arow + (size_t)(kt + 1) * 16);
            w_reg = *(const float4*)(wrow + (size_t)(kt + 1) * 16);
        }
#pragma unroll
        for (int k = 0; k < 16; ++k) {
            ulonglong2 a01 = *(const ulonglong2*)&Ad[k][(ty << 2)];
            ulonglong2 a23 = *(const ulonglong2*)&Ad[k][(ty << 2) + 2];
            ulonglong2 w01 = *(const ulonglong2*)&Ws[k][(tx << 2)];
            acc[0][0] = ffma2(a01.x, w01.x, acc[0][0]);
            acc[0][1] = ffma2(a01.x, w01.y, acc[0][1]);
            acc[1][0] = ffma2(a01.y, w01.x, acc[1][0]);
            acc[1][1] = ffma2(a01.y, w01.y, acc[1][1]);
            acc[2][0] = ffma2(a23.x, w01.x, acc[2][0]);
            acc[2][1] = ffma2(a23.x, w01.y, acc[2][1]);
            acc[3][0] = ffma2(a23.y, w01.x, acc[3][0]);
            acc[3][1] = ffma2(a23.y, w01.y, acc[3][1]);
        }
        __syncthreads();
    }

#pragma unroll
    for (int r = 0; r < 4; ++r) {
        const int row = m0 + (ty << 2) + r;
        size_t coff;
        if (cmode == 0) {
            coff = (size_t)row * N;
        } else {
            int t = row >> 7, b = row & (BB - 1);
            coff = ((size_t)b * TT + t) * N;
        }
        size_t cinoff = 0;
        if (Cin) {
            int cr = (cinmode == 0) ? row : (((row >> 11) << 7) + (row & (BB - 1)));
            cinoff = (size_t)cr * N;
        }
#pragma unroll
        for (int p = 0; p < 2; ++p) {
            const int col = n0 + (tx << 2) + (p << 1);
            float2 v = upk2(acc[r][p]);
            if (bias) { v.x += bias[col]; v.y += bias[col + 1]; }
            if (Cin)  { float2 ci = *(const float2*)(Cin + cinoff + col); v.x += ci.x; v.y += ci.y; }
            if (act)  { v.x = tanhf(v.x); v.y = tanhf(v.y); }
            *(float2*)(C + coff + col) = v;
        }
    }
}

// ---------------- grid barrier (all NBLK blocks co-resident) ----------------
#define NBLK 128
__device__ __forceinline__ void grid_barrier()
{
    __syncthreads();
    __threadfence();                 // every thread orders its own global stores
    if (threadIdx.x == 0) {
        unsigned int gen = g_bar_gen;
        if (atomicAdd(&g_bar_cnt, 1u) == NBLK - 1u) {
            g_bar_cnt = 0u;
            __threadfence();
            g_bar_gen = gen + 1u;
        } else {
            while (g_bar_gen == gen) { __nanosleep(64); }
        }
    }
    __syncthreads();
}

// ---------------- persistent LSTM recurrence ----------------
// Per step: gates[128,4096] = h_prev[128,1024] @ W[4096,1024]^T + gx[t]
// then fused cell -> c, h_all[t].  NBLK=128 blocks: 2 m-tiles x 64 n-tiles.
__global__ __launch_bounds__(256)
void lstm_recurrence(const float* __restrict__ W, const float* __restrict__ gx,
                     float* __restrict__ h_all, float* __restrict__ cbuf,
                     float* __restrict__ gates, int T)
{
    __shared__ unsigned long long Ad[16][64];
    __shared__ float Ws[16][64];

    const int tid = threadIdx.x;
    const int bx  = blockIdx.x;
    const int m0 = (bx >> 6) << 6;          // 0 or 64
    const int n0 = (bx & 63) << 6;          // 0..4032

    const int li = tid >> 2;
    const int lk = (tid & 3) << 2;
    const int ty = tid >> 4;
    const int tx = tid & 15;

    const float* wrow = W + (size_t)(n0 + li) * 1024 + lk;

    // cell-phase assignment (blocks 0..31): 64 rows x 64 j
    const int cr0 = (bx >> 4) << 6;         // 0 or 64 (valid for bx<32)
    const int cj0 = (bx & 15) << 6;         // 0..960

    for (int t = 0; t < T; ++t) {
        // ---- gate GEMM phase ----
        const float* hbase = (t == 0) ? g_zero : h_all + (size_t)(t - 1) * BB * 1024;
        const float* arow = hbase + (size_t)(m0 + li) * 1024 + lk;

        float4 a_reg = *(const float4*)arow;
        float4 w_reg = *(const float4*)wrow;

        unsigned long long acc[4][2];
#pragma unroll
        for (int r = 0; r < 4; ++r) { acc[r][0] = 0ull; acc[r][1] = 0ull; }

        for (int kt = 0; kt < 64; ++kt) {
            Ad[lk + 0][li] = pk2(a_reg.x, a_reg.x);
            Ad[lk + 1][li] = pk2(a_reg.y, a_reg.y);
            Ad[lk + 2][li] = pk2(a_reg.z, a_reg.z);
            Ad[lk + 3][li] = pk2(a_reg.w, a_reg.w);
            Ws[lk + 0][li] = w_reg.x;
            Ws[lk + 1][li] = w_reg.y;
            Ws[lk + 2][li] = w_reg.z;
            Ws[lk + 3][li] = w_reg.w;
            __syncthreads();
            if (kt + 1 < 64) {
                a_reg = *(const float4*)(arow + (size_t)(kt + 1) * 16);
                w_reg = *(const float4*)(wrow + (size_t)(kt + 1) * 16);
            }
#pragma unroll
            for (int k = 0; k < 16; ++k) {
                ulonglong2 a01 = *(const ulonglong2*)&Ad[k][(ty << 2)];
                ulonglong2 a23 = *(const ulonglong2*)&Ad[k][(ty << 2) + 2];
                ulonglong2 w01 = *(const ulonglong2*)&Ws[k][(tx << 2)];
                acc[0][0] = ffma2(a01.x, w01.x, acc[0][0]);
                acc[0][1] = ffma2(a01.x, w01.y, acc[0][1]);
                acc[1][0] = ffma2(a01.y, w01.x, acc[1][0]);
                acc[1][1] = ffma2(a01.y, w01.y, acc[1][1]);
                acc[2][0] = ffma2(a23.x, w01.x, acc[2][0]);
                acc[2][1] = ffma2(a23.x, w01.y, acc[2][1]);
                acc[3][0] = ffma2(a23.y, w01.x, acc[3][0]);
                acc[3][1] = ffma2(a23.y, w01.y, acc[3][1]);
            }
            __syncthreads();
        }

        // store gate tile (+gx addend) to global scratch
        const float* gxt = gx + (size_t)t * BB * 4096;
#pragma unroll
        for (int r = 0; r < 4; ++r) {
            const int row = m0 + (ty << 2) + r;
#pragma unroll
            for (int p = 0; p < 2; ++p) {
                const int col = n0 + (tx << 2) + (p << 1);
                float2 v = upk2(acc[r][p]);
                float2 gv = *(const float2*)(gxt + (size_t)row * 4096 + col);
                v.x += gv.x; v.y += gv.y;
                *(float2*)(gates + (size_t)row * 4096 + col) = v;
            }
        }

        grid_barrier();

        // ---- cell phase (blocks 0..31) ----
        if (bx < 32) {
#pragma unroll
            for (int it = 0; it < 16; ++it) {
                int idx = (it << 8) + tid;          // 0..4095
                int row = cr0 + (idx >> 6);
                int j   = cj0 + (idx & 63);
                const float* gr = gates + (size_t)row * 4096;
                float gi = __ldcg(gr + j);
                float gf = __ldcg(gr + 1024 + j);
                float gg = __ldcg(gr + 2048 + j);
                float go = __ldcg(gr + 3072 + j);
                float i = 1.f / (1.f + expf(-gi));
                float f = 1.f / (1.f + expf(-gf));
                float o = 1.f / (1.f + expf(-go));
                float cprev = (t == 0) ? 0.f : cbuf[(size_t)row * 1024 + j];
                float c = f * cprev + i * tanhf(gg);
                cbuf[(size_t)row * 1024 + j] = c;
                h_all[(size_t)t * BB * 1024 + (size_t)row * 1024 + j] = o * tanhf(c);
            }
        }

        grid_barrier();
    }
}

__global__ void add2(const float* __restrict__ a, const float* __restrict__ b,
                     float* __restrict__ o, int n)
{
    int i = blockIdx.x * blockDim.x + threadIdx.x;
    if (i < n) o[i] = a[i] + b[i];
}

// ---------------- host ----------------
extern "C" void kernel_launch(void* const* d_in, const int* in_sizes, int n_in,
                              void* d_out, int out_size)
{
    const float* z      = (const float*)d_in[0];
    const float* x      = (const float*)d_in[1];
    const float* fcz_w  = (const float*)d_in[2];
    const float* fcz_b  = (const float*)d_in[3];
    const float* c_wih  = (const float*)d_in[4];
    const float* c_whh  = (const float*)d_in[5];
    const float* c_bih  = (const float*)d_in[6];
    const float* c_bhh  = (const float*)d_in[7];
    const float* fcc_w  = (const float*)d_in[8];
    const float* fcc_b  = (const float*)d_in[9];
    const float* d0_wih = (const float*)d_in[10];
    const float* d0_whh = (const float*)d_in[11];
    const float* d0_bih = (const float*)d_in[12];
    const float* d0_bhh = (const float*)d_in[13];
    const float* d1_wih = (const float*)d_in[14];
    const float* d1_whh = (const float*)d_in[15];
    const float* d1_bih = (const float*)d_in[16];
    const float* d1_bhh = (const float*)d_in[17];
    const float* out_w  = (const float*)d_in[18];
    const float* out_b  = (const float*)d_in[19];
    float* out = (float*)d_out;

    float *cin, *gxc, *condh, *emb, *gxe, *gx, *h0, *h1, *gates, *cbuf, *bsum;
    cudaGetSymbolAddress((void**)&cin,   g_cin);
    cudaGetSymbolAddress((void**)&gxc,   g_gxc);
    cudaGetSymbolAddress((void**)&condh, g_condh);
    cudaGetSymbolAddress((void**)&emb,   g_emb);
    cudaGetSymbolAddress((void**)&gxe,   g_gxe);
    cudaGetSymbolAddress((void**)&gx,    g_gx);
    cudaGetSymbolAddress((void**)&h0,    g_h0);
    cudaGetSymbolAddress((void**)&h1,    g_h1);
    cudaGetSymbolAddress((void**)&gates, g_gates);
    cudaGetSymbolAddress((void**)&cbuf,  g_cbuf);
    cudaGetSymbolAddress((void**)&bsum,  g_bsum);

    dim3 blk(256);

    // combined biases: [0..4095] conductor, [4096..8191] dec0, [8192..12287] dec1
    add2<<<16, 256>>>(c_bih,  c_bhh,  bsum,        4096);
    add2<<<16, 256>>>(d0_bih, d0_bhh, bsum + 4096, 4096);
    add2<<<16, 256>>>(d1_bih, d1_bhh, bsum + 8192, 4096);

    // ---- conductor ----
    gemm_nt<<<dim3(HC / 64, (SSEQ * BB) / 64), blk>>>(
        z, fcz_w, fcz_b, nullptr, cin, SSEQ * BB, HC, ZZ, ZZ, 1, 0, 0, 0);
    gemm_nt<<<dim3(4 * HC / 64, (SSEQ * BB) / 64), blk>>>(
        cin, c_wih, bsum, nullptr, gxc, SSEQ * BB, 4 * HC, HC, HC, 0, 0, 0, 0);
    lstm_recurrence<<<NBLK, blk>>>(c_whh, gxc, condh, cbuf, gates, SSEQ);
    gemm_nt<<<dim3(EE / 64, (SSEQ * BB) / 64), blk>>>(
        condh, fcc_w, fcc_b, nullptr, emb, SSEQ * BB, EE, HC, HC, 0, 0, 0, 1);
    gemm_nt<<<dim3(4 * HD / 64, (SSEQ * BB) / 64), blk>>>(
        emb, d0_wih + VV, bsum + 4096, nullptr, gxe,
        SSEQ * BB, 4 * HD, EE, VV + EE, 0, 0, 0, 0);

    // ---- decoder layer 0 ----
    gemm_nt<<<dim3(4 * HD / 64, (TT * BB) / 64), blk>>>(
        x, d0_wih, nullptr, gxe, gx, TT * BB, 4 * HD, VV, VV + EE, 2, 1, 0, 0);
    lstm_recurrence<<<NBLK, blk>>>(d0_whh, gx, h0, cbuf, gates, TT);

    // ---- decoder layer 1 ----
    gemm_nt<<<dim3(4 * HD / 64, (TT * BB) / 64), blk>>>(
        h0, d1_wih, bsum + 8192, nullptr, gx, TT * BB, 4 * HD, HD, HD, 0, 0, 0, 0);
    lstm_recurrence<<<NBLK, blk>>>(d1_whh, gx, h1, cbuf, gates, TT);

    // ---- output projection (time-major -> [B,T,V]) ----
    gemm_nt<<<dim3(VV / 64, (TT * BB) / 64), blk>>>(
        h1, out_w, out_b, nullptr, out, TT * BB, VV, HD, HD, 0, 0, 1, 0);
}